// round 10
// baseline (speedup 1.0000x reference)
#include <cuda_runtime.h>
#include <cstdint>

#define BB 2
#define DD 512
#define KK 32
#define NN 4096
#define NB 64
#define GRID 128
#define NTHR 1024
#define ZSIZE (BB*DD*KK)

typedef unsigned long long ull;

// ---------- device scratch ----------
__device__ float g_Af[DD*KK];            // s^2
__device__ float g_Bf[DD*KK];            // -2 s^2 c
__device__ float g_C[KK];
__device__ float g_S1part[GRID*KK];
__device__ float g_M2t[(size_t)BB*64*KK*DD];  // M partials, [b*64+chunk][k][d] (8MB)
__device__ unsigned g_sync[2];           // barrier counters (zero-init)

// ---------- f32x2 helpers ----------
__device__ __forceinline__ ull pk2(float lo, float hi) {
    ull r; asm("mov.b64 %0, {%1,%2};" : "=l"(r) : "f"(lo), "f"(hi)); return r;
}
__device__ __forceinline__ void upk2(ull v, float& lo, float& hi) {
    asm("mov.b64 {%0,%1}, %2;" : "=f"(lo), "=f"(hi) : "l"(v));
}
__device__ __forceinline__ ull fma2(ull a, ull b, ull c) {
    ull d; asm("fma.rn.f32x2 %0, %1, %2, %3;" : "=l"(d) : "l"(a), "l"(b), "l"(c)); return d;
}
__device__ __forceinline__ void gbar(int id) {
    asm volatile("bar.sync %0, %1;" :: "r"(id), "r"(256) : "memory");
}

__device__ __forceinline__ void grid_sync_c(int i) {
    volatile unsigned* ctr = (volatile unsigned*)&g_sync[i];
    __syncthreads();
    if (threadIdx.x == 0) {
        __threadfence();
        atomicAdd(&g_sync[i], 1u);
        while (*ctr < GRID) { __nanosleep(32); }
        __threadfence();
    }
    __syncthreads();
}

// ---------- smem plan (210KB) ----------
// P1: XG [4][2][64][16] 32KB @0 ; Asf 64KB @32768 ; Bsf 64KB @98304
// P1 epi: Ep waves 32KB @0 ; Xs2 [512][64] 128KB @32768 (cp.async, after compute)
//         Ef @163840 (8KB) ; Qsp(ull) @172032 (8KB) ; red @180224 (4.2KB)
// P2' epi: Mt waves [16][32][17] 34.8KB @180224
// P3': small buffers @0
#define OFF_ASF 32768
#define OFF_BSF 98304
#define OFF_XS2 32768
#define OFF_EF  163840
#define OFF_QS  172032
#define OFF_RED 180224
#define OFF_MT  180224
#define SMEM_TOTAL 215040

__global__ __launch_bounds__(NTHR) void fused_kernel(const float* __restrict__ X,
                                                     const float* __restrict__ cw,
                                                     const float* __restrict__ scale,
                                                     float* __restrict__ out) {
    extern __shared__ unsigned char sm[];
    const int tid  = threadIdx.x;
    const int lane = tid & 31;
    const int w    = tid >> 5;           // 0..31
    const int grp  = w >> 3;             // 0..3
    const int wd   = w & 7;
    const int gt   = tid & 255;
    const int bid  = blockIdx.x;

    uint32_t smem_u32;
    asm("{ .reg .u64 t; cvta.to.shared.u64 t, %1; cvt.u32.u64 %0, t; }"
        : "=r"(smem_u32) : "l"(sm));

    // ============ P0: coefficients + C[k] ============
    if (bid == 0 && tid == 0) atomicExch(&g_sync[1], 0u);  // replay-safe pre-reset
    if (tid < 128) {
        int idx = bid*128 + tid;         // d*32+k
        int d = idx >> 5, k = idx & 31;
        float s = scale[idx];
        float c = cw[k*DD + d];
        g_Af[idx] = s*s;
        g_Bf[idx] = -2.f*s*s*c;
    }
    if (bid < KK) {
        float* red = (float*)sm;
        const int k = bid;
        float v = 0.f;
        if (tid < DD) {
            float s = scale[tid*KK + k];
            float c = cw[k*DD + tid];
            v = s*s*c*c;
        }
        red[tid] = v; __syncthreads();
        #pragma unroll
        for (int off = 512; off > 0; off >>= 1) {
            if (tid < off) red[tid] += red[tid + off];
            __syncthreads();
        }
        if (tid == 0) g_C[k] = red[0];
    }
    grid_sync_c(0);

    const int n0 = bid * NB;
    const int b  = n0 >> 12;

    // ============ P1: E-GEMM (group-scoped pipeline) ============
    ull acc[8];
    {
        float* XG  = (float*)sm;
        float* Asf = (float*)(sm + OFF_ASF);
        float* Bsf = (float*)(sm + OFF_BSF);

        const float* Xb = X + (size_t)b*DD*NN + (n0 & (NN - 1)) + grp*16;
        float* XGg = XG + grp*2048;

        #pragma unroll
        for (int it = 0; it < 4; it++) {
            ((float4*)Asf)[tid + it*1024] = ((const float4*)g_Af)[tid + it*1024];
            ((float4*)Bsf)[tid + it*1024] = ((const float4*)g_Bf)[tid + it*1024];
        }
        const int sr = gt >> 2, sc = gt & 3;
        float4 xpre = *(const float4*)(Xb + (size_t)sr*NN + sc*4);
        *(float4*)&XGg[sr*16 + sc*4] = xpre;
        __syncthreads();

        #pragma unroll
        for (int i = 0; i < 8; i++) acc[i] = 0ull;

        #pragma unroll 1
        for (int c = 0; c < 8; c++) {
            const float* Xs = XGg + (c & 1)*1024;
            if (c < 7)
                xpre = *(const float4*)(Xb + (size_t)((c+1)*64 + sr)*NN + sc*4);
            const float* Ac = Asf + c*64*KK;
            const float* Bc = Bsf + c*64*KK;
            #pragma unroll
            for (int it = 0; it < 8; it++) {
                int dd = wd + it*8;
                float av = Ac[dd*KK + lane];
                float bv = Bc[dd*KK + lane];
                ull a2 = pk2(av, av), b2 = pk2(bv, bv);
                const float* xr = &Xs[dd*16];
                #pragma unroll
                for (int g = 0; g < 4; g++) {
                    longlong2 xv = *reinterpret_cast<const longlong2*>(xr + g*4);
                    ull x01 = (ull)xv.x, x23 = (ull)xv.y;
                    ull t0 = fma2(a2, x01, b2);
                    acc[2*g]   = fma2(x01, t0, acc[2*g]);
                    ull t1 = fma2(a2, x23, b2);
                    acc[2*g+1] = fma2(x23, t1, acc[2*g+1]);
                }
            }
            if (c < 7)
                *(float4*)&XGg[(1 - (c & 1))*1024 + sr*16 + sc*4] = xpre;
            gbar(1 + grp);
        }
        __syncthreads();        // all groups done; XG + coeff regions dead
    }

    // ---- kick off X re-stage [512][64] via cp.async (overlaps epilogue) ----
    {
        const float* Xb2 = X + (size_t)b*DD*NN + (n0 & (NN - 1));
        #pragma unroll
        for (int it = 0; it < 8; it++) {
            int idx = tid + it*1024;
            int row = idx >> 4, c4 = idx & 15;
            uint32_t dst = smem_u32 + OFF_XS2 + (uint32_t)(row*64 + c4*4)*4u;
            const float* src = Xb2 + (size_t)row*NN + c4*4;
            asm volatile("cp.async.ca.shared.global [%0], [%1], 16;"
                         :: "r"(dst), "l"(src));
        }
        asm volatile("cp.async.commit_group;");
    }

    // ---- E cross-warp reduce (two 32KB waves @0), softmax ----
    {
        float* Ep  = (float*)sm;                 // [16][512]
        float* Ef  = (float*)(sm + OFF_EF);      // [64][32]
        ull*   Qsp = (ull*)(sm + OFF_QS);        // [32 np][32 k]
        float* red = (float*)(sm + OFF_RED);     // [32][33]

        if (w < 16) {
            #pragma unroll
            for (int i = 0; i < 8; i++) {
                float lo, hi; upk2(acc[i], lo, hi);
                Ep[w*512 + (2*i  )*KK + lane] = lo;
                Ep[w*512 + (2*i+1)*KK + lane] = hi;
            }
        }
        __syncthreads();
        {
            int n = tid >> 5, k = tid & 31;
            int gg = n >> 4, nl = n & 15;
            float s = 0.f;
            #pragma unroll
            for (int wdd = 0; wdd < 8; wdd++)
                s += Ep[(gg*8 + wdd)*512 + nl*KK + k];
            Ef[n*KK + k] = s;
        }
        __syncthreads();
        if (w >= 16) {
            #pragma unroll
            for (int i = 0; i < 8; i++) {
                float lo, hi; upk2(acc[i], lo, hi);
                Ep[(w-16)*512 + (2*i  )*KK + lane] = lo;
                Ep[(w-16)*512 + (2*i+1)*KK + lane] = hi;
            }
        }
        __syncthreads();
        {
            int n = tid >> 5, k = tid & 31;
            int gg = n >> 4, nl = n & 15;
            float s = 0.f;
            #pragma unroll
            for (int wdd = 0; wdd < 8; wdd++)
                s += Ep[(gg*8 + wdd)*512 + nl*KK + k];
            Ef[(32 + n)*KK + k] = s;
        }
        __syncthreads();

        // softmax: warp w handles n = 2w, 2w+1 (one Qsp np-row)
        float* Qout = out + ZSIZE;
        const float Ck = g_C[lane];
        float qv[2];
        float s1loc = 0.f;
        #pragma unroll
        for (int i = 0; i < 2; i++) {
            int n = w*2 + i;
            float arg = -0.5f * (Ef[n*KK + lane] + Ck);
            float m = arg;
            #pragma unroll
            for (int off = 16; off; off >>= 1) m = fmaxf(m, __shfl_xor_sync(~0u, m, off));
            float ex = __expf(arg - m);
            float ssum = ex;
            #pragma unroll
            for (int off = 16; off; off >>= 1) ssum += __shfl_xor_sync(~0u, ssum, off);
            float q = ex / ssum;
            Qout[(size_t)(n0 + n)*KK + lane] = q;
            qv[i] = q;
            s1loc += q;
        }
        Qsp[w*32 + lane] = pk2(qv[0], qv[1]);
        red[w*33 + lane] = s1loc;
        __syncthreads();
        if (w == 0) {
            float s = 0.f;
            #pragma unroll
            for (int i = 0; i < 32; i++) s += red[i*33 + lane];
            g_S1part[bid*KK + lane] = s;
        }
    }
    asm volatile("cp.async.wait_group 0;");
    __syncthreads();             // Xs2 + Qsp visible

    // ============ P2': M over this block's 64 n, all 512 d ============
    {
        const float* Xs2 = (const float*)(sm + OFF_XS2);   // [512][64]
        const ull*   Qsp = (const ull*)(sm + OFF_QS);
        const int chunk = bid & 63;
        const int dbase = w*16;

        ull acc2[16];
        #pragma unroll
        for (int i = 0; i < 16; i++) acc2[i] = 0ull;

        #pragma unroll 1
        for (int ng = 0; ng < 4; ng++) {
            ull q2[8];
            #pragma unroll
            for (int j = 0; j < 8; j++)
                q2[j] = Qsp[(ng*8 + j)*32 + lane];
            #pragma unroll
            for (int dl = 0; dl < 16; dl++) {
                const float* xr = &Xs2[(dbase + dl)*64 + ng*16];
                longlong2 xa = *(const longlong2*)(xr);
                longlong2 xb = *(const longlong2*)(xr + 4);
                longlong2 xc = *(const longlong2*)(xr + 8);
                longlong2 xd = *(const longlong2*)(xr + 12);
                ull a = acc2[dl];
                a = fma2(q2[0], (ull)xa.x, a);
                a = fma2(q2[1], (ull)xa.y, a);
                a = fma2(q2[2], (ull)xb.x, a);
                a = fma2(q2[3], (ull)xb.y, a);
                a = fma2(q2[4], (ull)xc.x, a);
                a = fma2(q2[5], (ull)xc.y, a);
                a = fma2(q2[6], (ull)xd.x, a);
                a = fma2(q2[7], (ull)xd.y, a);
                acc2[dl] = a;
            }
        }
        // transpose-store: two 16-warp waves through Mt [16][32][17]
        float mval[16];
        #pragma unroll
        for (int dl = 0; dl < 16; dl++) {
            float lo, hi; upk2(acc2[dl], lo, hi);
            mval[dl] = lo + hi;
        }
        float* Mt = (float*)(sm + OFF_MT);
        const int chunkbase = (b*64 + chunk)*32;
        #pragma unroll 1
        for (int wv = 0; wv < 2; wv++) {
            if ((w >> 4) == wv) {
                float* tile = Mt + (w & 15)*(32*17);
                #pragma unroll
                for (int dl = 0; dl < 16; dl++)
                    tile[lane*17 + dl] = mval[dl];
            }
            __syncthreads();
            #pragma unroll
            for (int it = 0; it < 8; it++) {
                int idx = tid + it*1024;        // 0..8191 = k*256 + dloc
                int k2 = idx >> 8, dloc = idx & 255;
                float v = Mt[(dloc >> 4)*(32*17) + k2*17 + (dloc & 15)];
                g_M2t[(size_t)(chunkbase + k2)*DD + wv*256 + dloc] = v;
            }
            __syncthreads();
        }
    }
    grid_sync_c(1);
    if (bid == 0 && tid == 0) atomicExch(&g_sync[0], 0u);

    // ============ P3': one (b,k) per block; blocks >=64 exit ============
    if (bid < 64) {
        const int b3 = bid >> 5, k3 = bid & 31;
        float* s1sm = (float*)sm;             // [64]
        float* Msm  = (float*)(sm + 256);     // [2][512]
        float* zsm  = (float*)(sm + 4352);    // [512]
        float* rsm  = (float*)(sm + 6400);    // [512]
        float* bc   = (float*)(sm + 8448);    // [1]

        if (tid < 64) s1sm[tid] = g_S1part[(b3*64 + tid)*KK + k3];
        // M reduce: thread (h = tid>>9, d = tid&511) sums 32 chunks, fixed order
        {
            const int h = tid >> 9, d = tid & 511;
            const float* msrc = g_M2t + ((size_t)(b3*64 + h*32)*KK + k3)*DD + d;
            float mp = 0.f;
            #pragma unroll
            for (int j = 0; j < 32; j++) mp += msrc[(size_t)j*KK*DD];
            Msm[h*512 + d] = mp;
        }
        __syncthreads();
        if (tid == 0) {
            float s = 0.f;
            #pragma unroll
            for (int i = 0; i < 64; i++) s += s1sm[i];
            bc[0] = 1.f / s;
        }
        __syncthreads();
        if (tid < 512) {
            int d = tid;
            float m = Msm[d] + Msm[512 + d];
            float z = scale[d*KK + k3] * (m*bc[0] - cw[k3*DD + d]);
            zsm[d] = z;
            rsm[d] = z*z;
        }
        __syncthreads();
        #pragma unroll
        for (int off = 256; off > 0; off >>= 1) {
            if (tid < off) rsm[tid] += rsm[tid + off];
            __syncthreads();
        }
        if (tid < 512) {
            float invn = rsqrtf(rsm[0]);
            out[((size_t)b3*DD + tid)*KK + k3] = zsm[tid] * invn;
        }
    }
}

extern "C" void kernel_launch(void* const* d_in, const int* in_sizes, int n_in,
                              void* d_out, int out_size) {
    const float* X     = (const float*)d_in[0];
    const float* cw    = (const float*)d_in[1];
    const float* scale = (const float*)d_in[2];
    float* out = (float*)d_out;

    cudaFuncSetAttribute(fused_kernel, cudaFuncAttributeMaxDynamicSharedMemorySize,
                         SMEM_TOTAL);
    fused_kernel<<<GRID, NTHR, SMEM_TOTAL>>>(X, cw, scale, out);
}